// round 17
// baseline (speedup 1.0000x reference)
#include <cuda_runtime.h>
#include <cuda_bf16.h>

#define B_ 4
#define N_ 512
#define D_ 128
#define H_ 128

typedef unsigned long long ull;
#define ABSMASK2 0x7fffffff7fffffffULL

// ---- packed f32x2 helpers -------------------------------------------------
__device__ __forceinline__ void fma2(ull &a, ull x, ull w) {
    asm("fma.rn.f32x2 %0, %1, %2, %0;" : "+l"(a) : "l"(x), "l"(w));
}
__device__ __forceinline__ ull add2(ull a, ull b) {
    ull r; asm("add.rn.f32x2 %0, %1, %2;" : "=l"(r) : "l"(a), "l"(b)); return r;
}
__device__ __forceinline__ ull pack2(float lo, float hi) {
    ull r; asm("mov.b64 %0, {%1, %2};" : "=l"(r) : "f"(lo), "f"(hi)); return r;
}
__device__ __forceinline__ void unpack2(ull v, float &lo, float &hi) {
    asm("mov.b64 {%0, %1}, %2;" : "=f"(lo), "=f"(hi) : "l"(v));
}
__device__ __forceinline__ float hadd2(ull v) { float lo, hi; unpack2(v, lo, hi); return lo + hi; }

// ---- scratch --------------------------------------------------------------
__device__ float gA[B_ * N_ * H_];
__device__ float gC[B_ * N_ * H_];
__device__ float gWA[B_ * N_];
__device__ float gWC[B_ * N_];
__device__ float gDiag[B_ * N_];

// ---------------------------------------------------------------------------
// Precompute v17: 16 rows/block via ROW-PAIR f32x2 packing, grid 128 (halves
// W L2 traffic: 49MB -> 24.6MB). 256 threads = h(128) x d-half(2). Acc regs
// identical to proven RW=8 config (3 x 8 ull = 48). X staged transposed so a
// row-pair read is one broadcast LDS.64. Distance-2 W register prefetch.
// ---------------------------------------------------------------------------
#define RWP 16

__global__ __launch_bounds__(256) void precompute_kernel(
    const float* __restrict__ X,
    const float* __restrict__ W1c, const float* __restrict__ b1c,
    const float* __restrict__ W1s, const float* __restrict__ b1s,
    const float* __restrict__ W2s, const float* __restrict__ b2s,
    const float* __restrict__ W2c)
{
    const int tid  = threadIdx.x;
    const int h    = tid & 127;
    const int half = tid >> 7;
    const int rowBase = blockIdx.x * RWP;

    __shared__ float xsT[D_][18];          // transposed X, 9.2 KB
    __shared__ ull   redA[8][H_];          // 8 KB (half-1 packed partials)
    __shared__ ull   redC[8][H_];          // 8 KB
    __shared__ ull   redS[8][H_];          // 8 KB
    __shared__ float red4d[4][RWP];
    __shared__ float red4a[4][RWP];
    __shared__ float red4c[4][RWP];

    // load 16 X rows, store transposed (gmem reads coalesced)
    for (int k = tid; k < RWP * D_; k += 256) {
        const int r = k >> 7;              // 0..15
        const int d = k & 127;
        xsT[d][r] = X[(size_t)rowBase * D_ + k];
    }
    __syncthreads();

    ull accA[8], accC[8], accS[8];
#pragma unroll
    for (int rp = 0; rp < 8; rp++) { accA[rp] = 0ull; accC[rp] = 0ull; accS[rp] = 0ull; }

    const int dBase = half * 64;
    const float* pA = W1c + (size_t)dBase * H_ + h;
    const float* pC = W1c + (size_t)(dBase + D_) * H_ + h;
    const float* pS = W1s + (size_t)dBase * H_ + h;

    float wb[3][12];
#pragma unroll
    for (int p = 0; p < 2; p++) {
#pragma unroll
        for (int q = 0; q < 4; q++) {
            wb[p][q]     = pA[(p * 4 + q) * H_];
            wb[p][4 + q] = pC[(p * 4 + q) * H_];
            wb[p][8 + q] = pS[(p * 4 + q) * H_];
        }
    }

#pragma unroll
    for (int cc = 0; cc < 16; cc++) {
        const int cur = cc % 3;
        if (cc < 14) {
            const int nb  = (cc + 2) % 3;
            const int off = (cc + 2) * 4;
#pragma unroll
            for (int q = 0; q < 4; q++) {
                wb[nb][q]     = pA[(off + q) * H_];
                wb[nb][4 + q] = pC[(off + q) * H_];
                wb[nb][8 + q] = pS[(off + q) * H_];
            }
        }
        const int d0 = dBase + cc * 4;
#pragma unroll
        for (int e = 0; e < 4; e++) {
            const ull wa2 = pack2(wb[cur][e],     wb[cur][e]);
            const ull wc2 = pack2(wb[cur][4 + e], wb[cur][4 + e]);
            const ull ws2 = pack2(wb[cur][8 + e], wb[cur][8 + e]);
            const int d = d0 + e;
#pragma unroll
            for (int rp = 0; rp < 8; rp++) {
                const ull xv = *(const ull*)&xsT[d][rp * 2];   // broadcast LDS.64
                fma2(accA[rp], xv, wa2);
                fma2(accC[rp], xv, wc2);
                fma2(accS[rp], xv, ws2);
            }
        }
    }

    if (half == 1) {
#pragma unroll
        for (int rp = 0; rp < 8; rp++) {
            redA[rp][h] = accA[rp];
            redC[rp][h] = accC[rp];
            redS[rp][h] = accS[rp];
        }
    }
    __syncthreads();

    if (half == 0) {
        const float bc  = b1c[h];
        const float bs  = b1s[h];
        const float w2s = W2s[h];
        const float w2c = W2c[h];
        const int warp = tid >> 5;
#pragma unroll
        for (int rp = 0; rp < 8; rp++) {
            float a0, a1, c0, c1, s0, s1;
            unpack2(add2(accA[rp], redA[rp][h]), a0, a1);
            unpack2(add2(accC[rp], redC[rp][h]), c0, c1);
            unpack2(add2(accS[rp], redS[rp][h]), s0, s1);
            c0 += bc; c1 += bc;
            const size_t r0 = (size_t)(rowBase + 2 * rp) * H_ + h;
            gA[r0]      = a0;
            gA[r0 + H_] = a1;
            gC[r0]      = c0;
            gC[r0 + H_] = c1;

            float t0  = fmaxf(s0 + bs, 0.f) * w2s;
            float t1  = fmaxf(s1 + bs, 0.f) * w2s;
            float ta0 = a0 * w2c, ta1 = a1 * w2c;
            float tc0 = c0 * w2c, tc1 = c1 * w2c;
#pragma unroll
            for (int off = 16; off > 0; off >>= 1) {
                t0  += __shfl_down_sync(0xffffffffu, t0,  off);
                t1  += __shfl_down_sync(0xffffffffu, t1,  off);
                ta0 += __shfl_down_sync(0xffffffffu, ta0, off);
                ta1 += __shfl_down_sync(0xffffffffu, ta1, off);
                tc0 += __shfl_down_sync(0xffffffffu, tc0, off);
                tc1 += __shfl_down_sync(0xffffffffu, tc1, off);
            }
            if ((tid & 31) == 0) {
                red4d[warp][2 * rp]     = t0;
                red4d[warp][2 * rp + 1] = t1;
                red4a[warp][2 * rp]     = ta0;
                red4a[warp][2 * rp + 1] = ta1;
                red4c[warp][2 * rp]     = tc0;
                red4c[warp][2 * rp + 1] = tc1;
            }
        }
    }
    __syncthreads();
    if (tid < RWP) {
        const float sd = red4d[0][tid] + red4d[1][tid] + red4d[2][tid] + red4d[3][tid] + b2s[0];
        gDiag[rowBase + tid] = 1.f / (1.f + __expf(-sd));
        gWA[rowBase + tid] = red4a[0][tid] + red4a[1][tid] + red4a[2][tid] + red4a[3][tid];
        gWC[rowBase + tid] = red4c[0][tid] + red4c[1][tid] + red4c[2][tid] + red4c[3][tid];
    }
}

// ---------------------------------------------------------------------------
// Pair kernel (v12 exact, measured 14.9us): 64x64 tile, 512 thr, 4x2 micro,
// abs-trick (relu(x)w = 0.5(xw + |x|w)), warp-broadcast A rows.
// ---------------------------------------------------------------------------
#define PSTRIDE 132
#define SMEM_PAIR_BYTES ((2 * 64 * PSTRIDE + 128 + 64 + 64 + 16) * 4)

__global__ __launch_bounds__(512) void pair_kernel(
    const float* __restrict__ W2c, const float* __restrict__ b2c,
    float* __restrict__ out)
{
    extern __shared__ float sm[];
    float* As = sm;                             // [64][132]
    float* Cs = sm + 64 * PSTRIDE;              // [64][132]
    float* ws = sm + 2 * 64 * PSTRIDE;          // [128]
    float* wa = ws + 128;                       // [64]
    float* wc = wa + 64;                        // [64]

    int t = blockIdx.x, ti = 0;
    while (t >= 8 - ti) { t -= 8 - ti; ti++; }
    const int tj = ti + t;
    const int b  = blockIdx.y;

    const int tid = threadIdx.x;
    const int i0 = ti * 64, j0 = tj * 64;

    {
        const float4* ga4 = (const float4*)(gA + ((size_t)b * N_ + i0) * H_);
        const float4* gc4 = (const float4*)(gC + ((size_t)b * N_ + j0) * H_);
#pragma unroll
        for (int k = 0; k < 4; k++) {
            const int e = k * 512 + tid;
            const int r = e >> 5, c = e & 31;
            ((float4*)&As[r * PSTRIDE])[c] = ga4[r * 32 + c];
            ((float4*)&Cs[r * PSTRIDE])[c] = gc4[r * 32 + c];
        }
        if (tid < 128)      ws[tid] = W2c[tid];
        else if (tid < 192) wa[tid - 128] = gWA[b * N_ + i0 + (tid - 128)];
        else if (tid < 256) wc[tid - 192] = gWC[b * N_ + j0 + (tid - 192)];
    }
    __syncthreads();

    const int ty = tid >> 5;     // warp id -> rows ty+16k (broadcast loads)
    const int tx = tid & 31;     // lane    -> cols tx+32m (conflict-free)

    const float* aBase = &As[ty * PSTRIDE];
    const float* cBase = &Cs[tx * PSTRIDE];

    ull acc[4][2];
#pragma unroll
    for (int k = 0; k < 4; k++) { acc[k][0] = 0ull; acc[k][1] = 0ull; }

#pragma unroll 4
    for (int hh = 0; hh < H_; hh += 4) {
        ulonglong2 av[4], cv[2];
#pragma unroll
        for (int k = 0; k < 4; k++)
            av[k] = *(const ulonglong2*)(aBase + (16 * k) * PSTRIDE + hh);
#pragma unroll
        for (int m = 0; m < 2; m++)
            cv[m] = *(const ulonglong2*)(cBase + (32 * m) * PSTRIDE + hh);
        const ulonglong2 wv = *(const ulonglong2*)&ws[hh];

#pragma unroll
        for (int k = 0; k < 4; k++) {
#pragma unroll
            for (int m = 0; m < 2; m++) {
                const ull x0 = add2(av[k].x, cv[m].x) & ABSMASK2;
                const ull x1 = add2(av[k].y, cv[m].y) & ABSMASK2;
                fma2(acc[k][m], x0, wv.x);
                fma2(acc[k][m], x1, wv.y);
            }
        }
    }

    const float bb = b2c[0];
    float sv[4][2];
#pragma unroll
    for (int k = 0; k < 4; k++) {
        const float wai = wa[ty + 16 * k];
#pragma unroll
        for (int m = 0; m < 2; m++) {
            const float pre = fmaf(0.5f, hadd2(acc[k][m]),
                                   0.5f * (wai + wc[tx + 32 * m]) + bb);
            sv[k][m] = 1.f / (1.f + __expf(-pre));
        }
    }

    __syncthreads();
    float* St = As;
#define ST(i, j) St[(i) * 65 + (j)]

    if (ti != tj) {
#pragma unroll
        for (int k = 0; k < 4; k++)
#pragma unroll
            for (int m = 0; m < 2; m++)
                ST(ty + 16 * k, tx + 32 * m) = sv[k][m];
        __syncthreads();

        for (int q = tid; q < 1024; q += 512) {
            const int r = q >> 4, c = (q & 15) * 4;
            float4 v = make_float4(ST(r, c), ST(r, c + 1), ST(r, c + 2), ST(r, c + 3));
            *(float4*)&out[((size_t)b * N_ + i0 + r) * N_ + j0 + c] = v;
        }
        for (int q = tid; q < 1024; q += 512) {
            const int r = q >> 4, c = (q & 15) * 4;
            float4 v = make_float4(ST(c, r), ST(c + 1, r), ST(c + 2, r), ST(c + 3, r));
            *(float4*)&out[((size_t)b * N_ + j0 + r) * N_ + i0 + c] = v;
        }
    } else {
        const int gi0 = b * N_ + i0;
#pragma unroll
        for (int k = 0; k < 4; k++) {
#pragma unroll
            for (int m = 0; m < 2; m++) {
                const int i = ty + 16 * k, j = tx + 32 * m;
                if (i < j)       { ST(i, j) = sv[k][m]; ST(j, i) = sv[k][m]; }
                else if (i == j) { ST(i, i) = gDiag[gi0 + i]; }
            }
        }
        __syncthreads();
        for (int q = tid; q < 1024; q += 512) {
            const int r = q >> 4, c = (q & 15) * 4;
            float4 v = make_float4(ST(r, c), ST(r, c + 1), ST(r, c + 2), ST(r, c + 3));
            *(float4*)&out[((size_t)b * N_ + i0 + r) * N_ + j0 + c] = v;
        }
    }
#undef ST
}

// ---------------------------------------------------------------------------
extern "C" void kernel_launch(void* const* d_in, const int* in_sizes, int n_in,
                              void* d_out, int out_size)
{
    const float* X   = (const float*)d_in[0];
    const float* W1c = (const float*)d_in[1];
    const float* b1c = (const float*)d_in[2];
    const float* W2c = (const float*)d_in[3];
    const float* b2c = (const float*)d_in[4];
    const float* W1s = (const float*)d_in[5];
    const float* b1s = (const float*)d_in[6];
    const float* W2s = (const float*)d_in[7];
    const float* b2s = (const float*)d_in[8];
    float* out = (float*)d_out;

    static bool attrSet = false;
    if (!attrSet) {
        cudaFuncSetAttribute(pair_kernel,
                             cudaFuncAttributeMaxDynamicSharedMemorySize,
                             SMEM_PAIR_BYTES);
        attrSet = true;
    }

    precompute_kernel<<<(B_ * N_) / RWP, 256>>>(X, W1c, b1c, W1s, b1s, W2s, b2s, W2c);

    dim3 grid(36, B_);   // triangular 64x64 tiles x batch
    pair_kernel<<<grid, 512, SMEM_PAIR_BYTES>>>(W2c, b2c, out);
}